// round 1
// baseline (speedup 1.0000x reference)
#include <cuda_runtime.h>
#include <cuda_bf16.h>
#include <cstdint>
#include <cstddef>

// Problem constants
#define BB 2
#define TT 2048
#define DD 768
#define HH 12
#define HS 64
#define FF 3072
#define HALF 1536
#define NT (BB*TT)   // 4096

// ---------------- scratch (device globals; no allocation allowed) ------------
__device__ float g_h  [(size_t)NT*DD];
__device__ float g_q  [(size_t)NT*DD];
__device__ float g_k  [(size_t)NT*DD];
__device__ float g_v  [(size_t)NT*DD];
__device__ float g_at [(size_t)NT*DD];
__device__ float g_x1 [(size_t)NT*DD];
__device__ float g_h2 [(size_t)NT*DD];
__device__ float g_u  [(size_t)NT*FF];
__device__ float g_sw [(size_t)NT*HALF];

// ---------------- RMSNorm: out = g * x / (sqrt(mean(x^2)) + 1e-8) ------------
__global__ void __launch_bounds__(256) rmsnorm_kernel(
    const float* __restrict__ x, const float* __restrict__ g, float* __restrict__ out)
{
    int row = blockIdx.x;
    const float* xr = x + (size_t)row * DD;
    float* orow = out + (size_t)row * DD;
    int tid = threadIdx.x;

    float ss = 0.f;
    for (int i = tid; i < DD; i += 256) { float v = xr[i]; ss += v * v; }
    // reduce
    #pragma unroll
    for (int o = 16; o > 0; o >>= 1) ss += __shfl_xor_sync(0xffffffffu, ss, o);
    __shared__ float red[8];
    if ((tid & 31) == 0) red[tid >> 5] = ss;
    __syncthreads();
    if (tid < 8) {
        float v = red[tid];
        #pragma unroll
        for (int o = 4; o > 0; o >>= 1) v += __shfl_xor_sync(0xffu, v, o);
        if (tid == 0) red[0] = v;
    }
    __syncthreads();
    float sumsq = red[0];
    float rms = sqrtf(sumsq * (1.0f / DD));
    float inv = 1.0f / (rms + 1e-8f);
    for (int i = tid; i < DD; i += 256)
        orow[i] = g[i] * xr[i] * inv;
}

// ---------------- Tiled fp32 GEMM: C[M,N] = A[M,K] @ B + bias + resid --------
// B element (k, n) lives at: (n>>6)*sH + k*sK + (n&63)
//   - plain row-major [K,N]:       sH = 64,    sK = N
//   - QKV weight layout (H,D,HS):  sH = K*64,  sK = 64
#define GBM 128
#define GBN 128
#define GBK 8

__global__ void __launch_bounds__(256) gemm_kernel(
    const float* __restrict__ A, const float* __restrict__ Bm,
    const float* __restrict__ bias, const float* __restrict__ resid,
    float* __restrict__ C, int M, int N, int K, int sH, int sK)
{
    __shared__ float As[GBK][GBM];
    __shared__ float Bs[GBK][GBN];

    int tid = threadIdx.x;
    int bm = blockIdx.y * GBM;
    int bn = blockIdx.x * GBN;

    int arow = tid >> 1;          // 0..127
    int acol = (tid & 1) * 4;     // 0 or 4
    int brow = tid >> 5;          // 0..7
    int bcol = (tid & 31) * 4;    // 0..124
    int tr = (tid >> 4) * 8;      // 0..120
    int tc = (tid & 15) * 8;      // 0..120

    float acc[8][8];
    #pragma unroll
    for (int i = 0; i < 8; i++)
        #pragma unroll
        for (int j = 0; j < 8; j++) acc[i][j] = 0.f;

    const float* aptr = A + (size_t)(bm + arow) * K + acol;
    int n_g = bn + bcol;
    size_t bbase = (size_t)(n_g >> 6) * sH + (size_t)(n_g & 63);

    for (int k0 = 0; k0 < K; k0 += GBK) {
        float4 av = *(const float4*)(aptr + k0);
        float4 bv = *(const float4*)(Bm + bbase + (size_t)(k0 + brow) * sK);

        As[acol + 0][arow] = av.x;
        As[acol + 1][arow] = av.y;
        As[acol + 2][arow] = av.z;
        As[acol + 3][arow] = av.w;
        *(float4*)&Bs[brow][bcol] = bv;
        __syncthreads();

        #pragma unroll
        for (int kk = 0; kk < GBK; kk++) {
            float a[8], b[8];
            *(float4*)&a[0] = *(const float4*)&As[kk][tr];
            *(float4*)&a[4] = *(const float4*)&As[kk][tr + 4];
            *(float4*)&b[0] = *(const float4*)&Bs[kk][tc];
            *(float4*)&b[4] = *(const float4*)&Bs[kk][tc + 4];
            #pragma unroll
            for (int i = 0; i < 8; i++)
                #pragma unroll
                for (int j = 0; j < 8; j++)
                    acc[i][j] += a[i] * b[j];
        }
        __syncthreads();
    }

    // epilogue
    #pragma unroll
    for (int i = 0; i < 8; i++) {
        int m = bm + tr + i;
        float* cp = C + (size_t)m * N + bn + tc;
        const float* rp = resid ? (resid + (size_t)m * N + bn + tc) : nullptr;
        #pragma unroll
        for (int j = 0; j < 8; j += 4) {
            float4 cv;
            cv.x = acc[i][j + 0];
            cv.y = acc[i][j + 1];
            cv.z = acc[i][j + 2];
            cv.w = acc[i][j + 3];
            if (bias) {
                const float4 bb = *(const float4*)(bias + bn + tc + j);
                cv.x += bb.x; cv.y += bb.y; cv.z += bb.z; cv.w += bb.w;
            }
            if (rp) {
                const float4 rr = *(const float4*)(rp + j);
                cv.x += rr.x; cv.y += rr.y; cv.z += rr.z; cv.w += rr.w;
            }
            *(float4*)(cp + j) = cv;
        }
    }
}

// ---------------- Causal flash attention (no-max online softmax) -------------
// Q/K/V layout: [B, T, H, HS] row-major ( == [NT, D] with col = h*64 + hs ).
// One thread per query row; 64 query rows per block; K/V tiles in smem
// (all lanes read the same address -> broadcast, conflict-free).
__global__ void __launch_bounds__(64) attn_kernel(
    const float* __restrict__ Q, const float* __restrict__ K,
    const float* __restrict__ V, float* __restrict__ O)
{
    int qtile = blockIdx.x;           // 0..T/64-1
    int bh = blockIdx.y;              // 0..B*H-1
    int b = bh / HH, h = bh % HH;
    int tid = threadIdx.x;            // 0..63
    int qrow = qtile * 64 + tid;

    __shared__ float Ks[64][64];
    __shared__ float Vs[64][64];

    const float scale = rsqrtf((float)DD);  // NOTE: reference scales by D^-0.5

    float q[64], o[64];
    {
        const float* qp = Q + ((size_t)(b * TT + qrow)) * DD + h * HS;
        #pragma unroll
        for (int c = 0; c < 64; c += 4) {
            float4 v4 = *(const float4*)(qp + c);
            q[c + 0] = v4.x * scale; q[c + 1] = v4.y * scale;
            q[c + 2] = v4.z * scale; q[c + 3] = v4.w * scale;
        }
    }
    #pragma unroll
    for (int c = 0; c < 64; c++) o[c] = 0.f;
    float l = 0.f;

    for (int kt = 0; kt <= qtile; kt++) {
        __syncthreads();
        // load K/V tiles (64x64) coalesced
        for (int idx = tid; idx < 64 * 16; idx += 64) {
            int r = idx >> 4;
            int c = (idx & 15) << 2;
            size_t goff = ((size_t)(b * TT + kt * 64 + r)) * DD + h * HS + c;
            *(float4*)&Ks[r][c] = *(const float4*)(K + goff);
            *(float4*)&Vs[r][c] = *(const float4*)(V + goff);
        }
        __syncthreads();

        int jmax = (kt == qtile) ? (tid + 1) : 64;   // causal mask
        for (int j = 0; j < jmax; j++) {
            float s = 0.f;
            #pragma unroll
            for (int c = 0; c < 64; c++) s += q[c] * Ks[j][c];
            float p = __expf(s);     // scores are O(1): safe without running max
            l += p;
            #pragma unroll
            for (int c = 0; c < 64; c++) o[c] += p * Vs[j][c];
        }
    }

    float inv = 1.0f / l;
    float* op = O + ((size_t)(b * TT + qrow)) * DD + h * HS;
    #pragma unroll
    for (int c = 0; c < 64; c += 4) {
        float4 v4;
        v4.x = o[c + 0] * inv; v4.y = o[c + 1] * inv;
        v4.z = o[c + 2] * inv; v4.w = o[c + 3] * inv;
        *(float4*)(op + c) = v4;
    }
}

// ---------------- SwiGLU: out[m,j] = silu(u[m,1536+j]) * u[m,j] --------------
__global__ void __launch_bounds__(256) swiglu_kernel(
    const float* __restrict__ u, float* __restrict__ out)
{
    int idx = blockIdx.x * 256 + threadIdx.x;
    if (idx >= NT * HALF) return;
    int m = idx / HALF, j = idx - m * HALF;
    float a  = u[(size_t)m * FF + j];
    float gt = u[(size_t)m * FF + HALF + j];
    float s  = gt / (1.0f + __expf(-gt));
    out[idx] = s * a;
}

// ---------------- launch -----------------------------------------------------
extern "C" void kernel_launch(void* const* d_in, const int* in_sizes, int n_in,
                              void* d_out, int out_size)
{
    const float* x  = (const float*)d_in[0];
    const float* Wq = (const float*)d_in[1];
    const float* Wk = (const float*)d_in[2];
    const float* Wv = (const float*)d_in[3];
    const float* Wo = (const float*)d_in[4];
    const float* bo = (const float*)d_in[5];
    const float* W1 = (const float*)d_in[6];
    const float* b1 = (const float*)d_in[7];
    const float* W2 = (const float*)d_in[8];
    const float* b2 = (const float*)d_in[9];
    const float* g1 = (const float*)d_in[10];
    const float* g2 = (const float*)d_in[11];
    float* out = (float*)d_out;

    float *h, *q, *k, *v, *at, *x1, *h2, *u, *sw;
    cudaGetSymbolAddress((void**)&h,  g_h);
    cudaGetSymbolAddress((void**)&q,  g_q);
    cudaGetSymbolAddress((void**)&k,  g_k);
    cudaGetSymbolAddress((void**)&v,  g_v);
    cudaGetSymbolAddress((void**)&at, g_at);
    cudaGetSymbolAddress((void**)&x1, g_x1);
    cudaGetSymbolAddress((void**)&h2, g_h2);
    cudaGetSymbolAddress((void**)&u,  g_u);
    cudaGetSymbolAddress((void**)&sw, g_sw);

    // 1) h = rmsnorm(x, g1)
    rmsnorm_kernel<<<NT, 256>>>(x, g1, h);

    // 2) q/k/v = h @ W{q,k,v}  (QKV weight layout: sH=K*64, sK=64)
    dim3 gqkv(DD / GBN, NT / GBM);
    gemm_kernel<<<gqkv, 256>>>(h, Wq, nullptr, nullptr, q, NT, DD, DD, DD * 64, 64);
    gemm_kernel<<<gqkv, 256>>>(h, Wk, nullptr, nullptr, k, NT, DD, DD, DD * 64, 64);
    gemm_kernel<<<gqkv, 256>>>(h, Wv, nullptr, nullptr, v, NT, DD, DD, DD * 64, 64);

    // 3) causal attention
    attn_kernel<<<dim3(TT / 64, BB * HH), 64>>>(q, k, v, at);

    // 4) x1 = x + at @ Wo + bo   (plain layout: sH=64, sK=N)
    gemm_kernel<<<dim3(DD / GBN, NT / GBM), 256>>>(at, Wo, bo, x, x1, NT, DD, DD, 64, DD);

    // 5) h2 = rmsnorm(x1, g2)
    rmsnorm_kernel<<<NT, 256>>>(x1, g2, h2);

    // 6) u = h2 @ W1 + b1
    gemm_kernel<<<dim3(FF / GBN, NT / GBM), 256>>>(h2, W1, b1, nullptr, u, NT, FF, DD, 64, FF);

    // 7) sw = silu(gate) * a
    swiglu_kernel<<<(NT * HALF + 255) / 256, 256>>>(u, sw);

    // 8) out = x1 + sw @ W2 + b2
    gemm_kernel<<<dim3(DD / GBN, NT / GBM), 256>>>(sw, W2, b2, x1, out, NT, DD, HALF, 64, DD);
}

// round 3
// speedup vs baseline: 1.5915x; 1.5915x over previous
#include <cuda_runtime.h>
#include <cuda_bf16.h>
#include <cstdint>
#include <cstddef>

// Problem constants
#define BB 2
#define TT 2048
#define DD 768
#define HH 12
#define HS 64
#define FF 3072
#define HALF 1536
#define NT (BB*TT)       // 4096
#define QKVN 2304        // fused q|k|v output width

// ---------------- scratch (device globals) -----------------------------------
__device__ float g_qkv[(size_t)NT*QKVN];
__device__ float g_x1 [(size_t)NT*DD];
__device__ float g_u  [(size_t)NT*FF];
// activation splits: hi block [M*K] then lo block [M*K]
__device__ __nv_bfloat16 g_ah [(size_t)2*NT*DD];    // rmsnorm1 out
__device__ __nv_bfloat16 g_atb[(size_t)2*NT*DD];    // attention out
__device__ __nv_bfloat16 g_h2b[(size_t)2*NT*DD];    // rmsnorm2 out
__device__ __nv_bfloat16 g_swb[(size_t)2*NT*HALF];  // swiglu out
// weight splits: hi block [N*K] then lo block [N*K], layout [N][K]
__device__ __nv_bfloat16 g_bqkv[(size_t)2*QKVN*DD];
__device__ __nv_bfloat16 g_bo  [(size_t)2*DD*DD];
__device__ __nv_bfloat16 g_b1  [(size_t)2*FF*DD];
__device__ __nv_bfloat16 g_b2  [(size_t)2*DD*HALF];

// ---------------- helpers ----------------------------------------------------
__device__ __forceinline__ uint32_t smem_u32(const void* p) {
    uint32_t a;
    asm("{ .reg .u64 t; cvta.to.shared.u64 t, %1; cvt.u32.u64 %0, t; }" : "=r"(a) : "l"(p));
    return a;
}
#define CPASYNC(d, s) asm volatile("cp.async.cg.shared.global [%0], [%1], 16;" :: "r"(d), "l"(s) : "memory")
#define CPCOMMIT()    asm volatile("cp.async.commit_group;" ::: "memory")
#define CPWAIT(n)     asm volatile("cp.async.wait_group %0;" :: "n"(n) : "memory")
#define LDSM4(r, a)                                                              \
    asm volatile("ldmatrix.sync.aligned.m8n8.x4.shared.b16 {%0,%1,%2,%3}, [%4];" \
        : "=r"((r)[0]), "=r"((r)[1]), "=r"((r)[2]), "=r"((r)[3]) : "r"(a))
#define MMA16816(c, a, b0, b1)                                                   \
    asm volatile("mma.sync.aligned.m16n8k16.row.col.f32.bf16.bf16.f32 "          \
        "{%0,%1,%2,%3}, {%4,%5,%6,%7}, {%8,%9}, {%0,%1,%2,%3};"                  \
        : "+f"((c)[0]), "+f"((c)[1]), "+f"((c)[2]), "+f"((c)[3])                 \
        : "r"((a)[0]), "r"((a)[1]), "r"((a)[2]), "r"((a)[3]), "r"(b0), "r"(b1))

__device__ __forceinline__ void split2(float v, __nv_bfloat16& h, __nv_bfloat16& l) {
    h = __float2bfloat16_rn(v);
    l = __float2bfloat16_rn(v - __bfloat162float(h));
}

// ---------------- weight prep: transpose/split to [N][K] bf16 hi/lo ----------
// mode 0: src(k,n) = W[k*srcLd + n]
// mode 1: qkv head layout: src(k,n) = W[(n>>6)*K*64 + k*64 + (n&63)]
__global__ void __launch_bounds__(256) prep_b(
    const float* __restrict__ W, __nv_bfloat16* __restrict__ hi,
    __nv_bfloat16* __restrict__ lo, int N, int K, int mode, int srcLd)
{
    int idx = blockIdx.x * 256 + threadIdx.x;
    int kq = K >> 2;
    if (idx >= N * kq) return;
    int n = idx / kq, k = (idx - n * kq) << 2;
    union { __nv_bfloat16 b[4]; uint2 u; } H, L;
    #pragma unroll
    for (int j = 0; j < 4; j++) {
        size_t sa = (mode == 0)
            ? (size_t)(k + j) * srcLd + n
            : (size_t)(n >> 6) * ((size_t)K * 64) + (size_t)(k + j) * 64 + (n & 63);
        split2(W[sa], H.b[j], L.b[j]);
    }
    *(uint2*)(hi + (size_t)n * K + k) = H.u;
    *(uint2*)(lo + (size_t)n * K + k) = L.u;
}

// ---------------- mma.sync bf16-split GEMM -----------------------------------
// C[M,N] = A @ B^T (+bias)(+resid); A pre-split hi/lo [M][K], B pre-split [N][K].
// CTA tile 128x128, warp tile 64x32, K-block 32, double-buffered cp.async.
#define KB 32
#define PADE 40                  // bf16 elems per smem row (80 B)
#define TILEB (128*PADE*2)       // 10240 B per tile
#define STGB  (4*TILEB)          // Ah,Al,Bh,Bl per stage
#define GEMM_SMEM (2*STGB)       // 81920 B

__global__ void __launch_bounds__(256) gemm_mma(
    const __nv_bfloat16* __restrict__ Ap, const __nv_bfloat16* __restrict__ Bp,
    const float* __restrict__ bias, const float* __restrict__ resid,
    float* __restrict__ C, int M, int N, int K)
{
    extern __shared__ char sm[];
    const size_t MK = (size_t)M * K, NK = (size_t)N * K;
    int tid = threadIdx.x, lane = tid & 31, wid = tid >> 5;
    int wm = wid >> 2, wn = wid & 3;               // 2 x 4 warp grid
    int bm = blockIdx.y * 128, bn = blockIdx.x * 128;
    uint32_t sbase = smem_u32(sm);

    float acc[4][4][4];
    #pragma unroll
    for (int i = 0; i < 4; i++)
        #pragma unroll
        for (int j = 0; j < 4; j++)
            #pragma unroll
            for (int q = 0; q < 4; q++) acc[i][j][q] = 0.f;

    // ldmatrix lane address components
    int a_r = lane & 15, a_c = (lane & 16) ? 8 : 0;
    int b_r = ((lane >> 4) << 3) + (lane & 7), b_c = (lane & 8);

    const int KBn = K / KB;

    // stage loader: 8 cp.async per thread
    auto load_stage = [&](int kb, int stg) {
        #pragma unroll
        for (int t4 = 0; t4 < 4; t4++) {
            const __nv_bfloat16* base =
                (t4 < 2) ? (Ap + (t4 ? MK : 0)) : (Bp + (t4 == 3 ? NK : 0));
            int rowbase = (t4 < 2) ? bm : bn;
            #pragma unroll
            for (int i = 0; i < 2; i++) {
                int c = i * 256 + tid;            // 0..511
                int row = c >> 2, cc = c & 3;
                uint32_t dst = sbase + stg * STGB + t4 * TILEB
                             + (uint32_t)(row * (PADE * 2) + cc * 16);
                const __nv_bfloat16* src =
                    base + (size_t)(rowbase + row) * K + kb * KB + cc * 8;
                CPASYNC(dst, src);
            }
        }
    };

    load_stage(0, 0);
    CPCOMMIT();

    for (int kb = 0; kb < KBn; kb++) {
        if (kb + 1 < KBn) {
            load_stage(kb + 1, (kb + 1) & 1);
            CPCOMMIT();
            CPWAIT(1);
        } else {
            CPWAIT(0);
        }
        __syncthreads();

        uint32_t sa = sbase + (kb & 1) * STGB;
        // terms: (Ahi,Bhi), (Ahi,Blo), (Alo,Bhi)
        #pragma unroll
        for (int term = 0; term < 3; term++) {
            uint32_t ao = sa + ((term == 2) ? TILEB : 0);
            uint32_t bo = sa + 2 * TILEB + ((term == 1) ? TILEB : 0);
            #pragma unroll
            for (int ks = 0; ks < KB; ks += 16) {
                uint32_t afr[4][4];
                #pragma unroll
                for (int mt = 0; mt < 4; mt++) {
                    uint32_t ad = ao + (uint32_t)(((wm * 64 + mt * 16 + a_r) * PADE
                                                   + ks + a_c) * 2);
                    LDSM4(afr[mt], ad);
                }
                uint32_t bfr[2][4];
                #pragma unroll
                for (int np = 0; np < 2; np++) {
                    uint32_t bd = bo + (uint32_t)(((wn * 32 + np * 16 + b_r) * PADE
                                                   + ks + b_c) * 2);
                    LDSM4(bfr[np], bd);
                }
                #pragma unroll
                for (int mt = 0; mt < 4; mt++)
                    #pragma unroll
                    for (int nt = 0; nt < 4; nt++)
                        MMA16816(acc[mt][nt], afr[mt],
                                 bfr[nt >> 1][(nt & 1) * 2],
                                 bfr[nt >> 1][(nt & 1) * 2 + 1]);
            }
        }
        __syncthreads();
    }

    // epilogue
    int g = lane >> 2, t = lane & 3;
    #pragma unroll
    for (int mt = 0; mt < 4; mt++) {
        #pragma unroll
        for (int half = 0; half < 2; half++) {
            int row = bm + wm * 64 + mt * 16 + g + half * 8;
            float* cp = C + (size_t)row * N;
            const float* rp = resid ? (resid + (size_t)row * N) : nullptr;
            #pragma unroll
            for (int nt = 0; nt < 4; nt++) {
                int col = bn + wn * 32 + nt * 8 + t * 2;
                float2 v;
                v.x = acc[mt][nt][half * 2 + 0];
                v.y = acc[mt][nt][half * 2 + 1];
                if (bias) {
                    float2 b2v = *(const float2*)(bias + col);
                    v.x += b2v.x; v.y += b2v.y;
                }
                if (rp) {
                    float2 r2v = *(const float2*)(rp + col);
                    v.x += r2v.x; v.y += r2v.y;
                }
                *(float2*)(cp + col) = v;
            }
        }
    }
}

// ---------------- RMSNorm -> bf16 hi/lo --------------------------------------
__global__ void __launch_bounds__(256) rmsnorm_split(
    const float* __restrict__ x, const float* __restrict__ g,
    __nv_bfloat16* __restrict__ o)  // hi at [row*DD+i], lo at +NT*DD
{
    int row = blockIdx.x;
    const float* xr = x + (size_t)row * DD;
    int tid = threadIdx.x;
    float ss = 0.f;
    for (int i = tid; i < DD; i += 256) { float v = xr[i]; ss += v * v; }
    #pragma unroll
    for (int o2 = 16; o2 > 0; o2 >>= 1) ss += __shfl_xor_sync(0xffffffffu, ss, o2);
    __shared__ float red[8];
    if ((tid & 31) == 0) red[tid >> 5] = ss;
    __syncthreads();
    if (tid < 8) {
        float v = red[tid];
        #pragma unroll
        for (int o2 = 4; o2 > 0; o2 >>= 1) v += __shfl_xor_sync(0xffu, v, o2);
        if (tid == 0) red[0] = v;
    }
    __syncthreads();
    float rms = sqrtf(red[0] * (1.0f / DD));
    float inv = 1.0f / (rms + 1e-8f);
    const size_t LO = (size_t)NT * DD;
    for (int i = tid; i < DD; i += 256) {
        float v = g[i] * xr[i] * inv;
        __nv_bfloat16 h, l; split2(v, h, l);
        o[(size_t)row * DD + i] = h;
        o[LO + (size_t)row * DD + i] = l;
    }
}

// ---------------- Causal flash attention (SIMT, fused-qkv input) -------------
// output: bf16 hi/lo split, ready as GEMM A operand
__global__ void __launch_bounds__(64) attn_kernel(
    const float* __restrict__ QKV, __nv_bfloat16* __restrict__ O)
{
    int qtile = blockIdx.x;
    int bh = blockIdx.y;
    int b = bh / HH, h = bh % HH;
    int tid = threadIdx.x;
    int qrow = qtile * 64 + tid;

    __shared__ float Ks[64][64];
    __shared__ float Vs[64][64];

    const float scale = rsqrtf((float)DD);
    const int qoff = h * HS;
    const int koff = DD + h * HS;
    const int voff = 2 * DD + h * HS;

    float q[64], o[64];
    {
        const float* qp = QKV + (size_t)(b * TT + qrow) * QKVN + qoff;
        #pragma unroll
        for (int c = 0; c < 64; c += 4) {
            float4 v4 = *(const float4*)(qp + c);
            q[c + 0] = v4.x * scale; q[c + 1] = v4.y * scale;
            q[c + 2] = v4.z * scale; q[c + 3] = v4.w * scale;
        }
    }
    #pragma unroll
    for (int c = 0; c < 64; c++) o[c] = 0.f;
    float l = 0.f;

    for (int kt = 0; kt <= qtile; kt++) {
        __syncthreads();
        for (int idx = tid; idx < 64 * 16; idx += 64) {
            int r = idx >> 4;
            int c = (idx & 15) << 2;
            size_t rowb = (size_t)(b * TT + kt * 64 + r) * QKVN;
            *(float4*)&Ks[r][c] = *(const float4*)(QKV + rowb + koff + c);
            *(float4*)&Vs[r][c] = *(const float4*)(QKV + rowb + voff + c);
        }
        __syncthreads();

        int jmax = (kt == qtile) ? (tid + 1) : 64;
        for (int j = 0; j < jmax; j++) {
            float s = 0.f;
            #pragma unroll
            for (int c = 0; c < 64; c++) s += q[c] * Ks[j][c];
            float p = __expf(s);
            l += p;
            #pragma unroll
            for (int c = 0; c < 64; c++) o[c] += p * Vs[j][c];
        }
    }

    float inv = 1.0f / l;
    const size_t LO = (size_t)NT * DD;
    size_t obase = (size_t)(b * TT + qrow) * DD + h * HS;
    #pragma unroll
    for (int c = 0; c < 64; c++) {
        __nv_bfloat16 hh, ll; split2(o[c] * inv, hh, ll);
        O[obase + c] = hh;
        O[LO + obase + c] = ll;
    }
}

// ---------------- SwiGLU -> bf16 hi/lo ---------------------------------------
__global__ void __launch_bounds__(256) swiglu_split(
    const float* __restrict__ u, __nv_bfloat16* __restrict__ out)
{
    int idx = blockIdx.x * 256 + threadIdx.x;
    if (idx >= NT * HALF) return;
    int m = idx / HALF, j = idx - m * HALF;
    float a  = u[(size_t)m * FF + j];
    float gt = u[(size_t)m * FF + HALF + j];
    float s  = gt / (1.0f + __expf(-gt));
    __nv_bfloat16 h, l; split2(s * a, h, l);
    out[idx] = h;
    out[(size_t)NT * HALF + idx] = l;
}

// ---------------- launch -----------------------------------------------------
extern "C" void kernel_launch(void* const* d_in, const int* in_sizes, int n_in,
                              void* d_out, int out_size)
{
    const float* x  = (const float*)d_in[0];
    const float* Wq = (const float*)d_in[1];
    const float* Wk = (const float*)d_in[2];
    const float* Wv = (const float*)d_in[3];
    const float* Wo = (const float*)d_in[4];
    const float* bo = (const float*)d_in[5];
    const float* W1 = (const float*)d_in[6];
    const float* b1 = (const float*)d_in[7];
    const float* W2 = (const float*)d_in[8];
    const float* b2 = (const float*)d_in[9];
    const float* g1 = (const float*)d_in[10];
    const float* g2 = (const float*)d_in[11];
    float* out = (float*)d_out;

    float *qkv, *x1, *u;
    __nv_bfloat16 *ah, *atb, *h2b, *swb, *bqkv, *bo_, *b1_, *b2_;
    cudaGetSymbolAddress((void**)&qkv, g_qkv);
    cudaGetSymbolAddress((void**)&x1,  g_x1);
    cudaGetSymbolAddress((void**)&u,   g_u);
    cudaGetSymbolAddress((void**)&ah,  g_ah);
    cudaGetSymbolAddress((void**)&atb, g_atb);
    cudaGetSymbolAddress((void**)&h2b, g_h2b);
    cudaGetSymbolAddress((void**)&swb, g_swb);
    cudaGetSymbolAddress((void**)&bqkv, g_bqkv);
    cudaGetSymbolAddress((void**)&bo_,  g_bo);
    cudaGetSymbolAddress((void**)&b1_,  g_b1);
    cudaGetSymbolAddress((void**)&b2_,  g_b2);

    cudaFuncSetAttribute(gemm_mma, cudaFuncAttributeMaxDynamicSharedMemorySize, GEMM_SMEM);

    const size_t QNK = (size_t)QKVN * DD;

    // weight prep
    {
        int g = (DD * (DD / 4) + 255) / 256;
        prep_b<<<g, 256>>>(Wq, bqkv,                  bqkv + QNK,                  DD, DD, 1, 0);
        prep_b<<<g, 256>>>(Wk, bqkv + (size_t)DD*DD,  bqkv + QNK + (size_t)DD*DD,  DD, DD, 1, 0);
        prep_b<<<g, 256>>>(Wv, bqkv + (size_t)2*DD*DD, bqkv + QNK + (size_t)2*DD*DD, DD, DD, 1, 0);
        prep_b<<<g, 256>>>(Wo, bo_, bo_ + (size_t)DD*DD, DD, DD, 0, DD);
        int g1n = (FF * (DD / 4) + 255) / 256;
        prep_b<<<g1n, 256>>>(W1, b1_, b1_ + (size_t)FF*DD, FF, DD, 0, FF);
        int g2n = (DD * (HALF / 4) + 255) / 256;
        prep_b<<<g2n, 256>>>(W2, b2_, b2_ + (size_t)DD*HALF, DD, HALF, 0, DD);
    }

    // 1) ah = split(rmsnorm(x, g1))
    rmsnorm_split<<<NT, 256>>>(x, g1, ah);

    // 2) qkv = ah @ [Wq|Wk|Wv]
    gemm_mma<<<dim3(QKVN / 128, NT / 128), 256, GEMM_SMEM>>>(
        ah, bqkv, nullptr, nullptr, qkv, NT, QKVN, DD);

    // 3) attention -> atb (split)
    attn_kernel<<<dim3(TT / 64, BB * HH), 64>>>(qkv, atb);

    // 4) x1 = x + atb @ Wo + bo
    gemm_mma<<<dim3(DD / 128, NT / 128), 256, GEMM_SMEM>>>(
        atb, bo_, bo, x, x1, NT, DD, DD);

    // 5) h2b = split(rmsnorm(x1, g2))
    rmsnorm_split<<<NT, 256>>>(x1, g2, h2b);

    // 6) u = h2b @ W1 + b1
    gemm_mma<<<dim3(FF / 128, NT / 128), 256, GEMM_SMEM>>>(
        h2b, b1_, b1, nullptr, u, NT, FF, DD);

    // 7) swb = split(swiglu(u))
    swiglu_split<<<(NT * HALF + 255) / 256, 256>>>(u, swb);

    // 8) out = x1 + swb @ W2 + b2
    gemm_mma<<<dim3(DD / 128, NT / 128), 256, GEMM_SMEM>>>(
        swb, b2_, b2, x1, out, NT, DD, HALF);
}

// round 4
// speedup vs baseline: 1.8641x; 1.1713x over previous
#include <cuda_runtime.h>
#include <cuda_bf16.h>
#include <cstdint>
#include <cstddef>

// Problem constants
#define BB 2
#define TT 2048
#define DD 768
#define HH 12
#define HS 64
#define FF 3072
#define HALF 1536
#define NT (BB*TT)       // 4096
#define QKVN 2304        // fused q|k|v output width
#define BH 24            // B*H
#define SCL 0.03608439182435161f   // 768^-0.5

// ---------------- scratch (device globals) -----------------------------------
__device__ float g_qkv[(size_t)NT*QKVN];
__device__ float g_x1 [(size_t)NT*DD];
__device__ float g_u  [(size_t)NT*FF];
// activation splits: hi block then lo block
__device__ __nv_bfloat16 g_ah [(size_t)2*NT*DD];    // rmsnorm1 out
__device__ __nv_bfloat16 g_atb[(size_t)2*NT*DD];    // attention out
__device__ __nv_bfloat16 g_h2b[(size_t)2*NT*DD];    // rmsnorm2 out
__device__ __nv_bfloat16 g_swb[(size_t)2*NT*HALF];  // swiglu out
// per-head K/V splits: K [bh][t][64] hi|lo ; V transposed [bh][c][T] hi|lo
__device__ __nv_bfloat16 g_kb [(size_t)2*BH*TT*HS];
__device__ __nv_bfloat16 g_vb [(size_t)2*BH*TT*HS];
// weight splits: hi block [N*K] then lo block [N*K], layout [N][K]
__device__ __nv_bfloat16 g_bqkv[(size_t)2*QKVN*DD];
__device__ __nv_bfloat16 g_bo  [(size_t)2*DD*DD];
__device__ __nv_bfloat16 g_b1  [(size_t)2*FF*DD];
__device__ __nv_bfloat16 g_b2  [(size_t)2*DD*HALF];

// ---------------- helpers ----------------------------------------------------
__device__ __forceinline__ uint32_t smem_u32(const void* p) {
    uint32_t a;
    asm("{ .reg .u64 t; cvta.to.shared.u64 t, %1; cvt.u32.u64 %0, t; }" : "=r"(a) : "l"(p));
    return a;
}
#define CPASYNC(d, s) asm volatile("cp.async.cg.shared.global [%0], [%1], 16;" :: "r"(d), "l"(s) : "memory")
#define CPCOMMIT()    asm volatile("cp.async.commit_group;" ::: "memory")
#define CPWAIT(n)     asm volatile("cp.async.wait_group %0;" :: "n"(n) : "memory")
#define LDSM4(r, a)                                                              \
    asm volatile("ldmatrix.sync.aligned.m8n8.x4.shared.b16 {%0,%1,%2,%3}, [%4];" \
        : "=r"((r)[0]), "=r"((r)[1]), "=r"((r)[2]), "=r"((r)[3]) : "r"(a))
#define MMA16816(c, a, b0, b1)                                                   \
    asm volatile("mma.sync.aligned.m16n8k16.row.col.f32.bf16.bf16.f32 "          \
        "{%0,%1,%2,%3}, {%4,%5,%6,%7}, {%8,%9}, {%0,%1,%2,%3};"                  \
        : "+f"((c)[0]), "+f"((c)[1]), "+f"((c)[2]), "+f"((c)[3])                 \
        : "r"((a)[0]), "r"((a)[1]), "r"((a)[2]), "r"((a)[3]), "r"(b0), "r"(b1))

__device__ __forceinline__ void split2(float v, __nv_bfloat16& h, __nv_bfloat16& l) {
    h = __float2bfloat16_rn(v);
    l = __float2bfloat16_rn(v - __bfloat162float(h));
}
__device__ __forceinline__ uint32_t packbf(__nv_bfloat16 lo, __nv_bfloat16 hi) {
    return (uint32_t)__bfloat16_as_ushort(lo) | ((uint32_t)__bfloat16_as_ushort(hi) << 16);
}

// ---------------- weight prep: transpose/split to [N][K] bf16 hi/lo ----------
__global__ void __launch_bounds__(256) prep_b(
    const float* __restrict__ W, __nv_bfloat16* __restrict__ hi,
    __nv_bfloat16* __restrict__ lo, int N, int K, int mode, int srcLd)
{
    int idx = blockIdx.x * 256 + threadIdx.x;
    int kq = K >> 2;
    if (idx >= N * kq) return;
    int n = idx / kq, k = (idx - n * kq) << 2;
    union { __nv_bfloat16 b[4]; uint2 u; } H, L;
    #pragma unroll
    for (int j = 0; j < 4; j++) {
        size_t sa = (mode == 0)
            ? (size_t)(k + j) * srcLd + n
            : (size_t)(n >> 6) * ((size_t)K * 64) + (size_t)(k + j) * 64 + (n & 63);
        split2(W[sa], H.b[j], L.b[j]);
    }
    *(uint2*)(hi + (size_t)n * K + k) = H.u;
    *(uint2*)(lo + (size_t)n * K + k) = L.u;
}

// ---------------- mma.sync bf16-split GEMM -----------------------------------
#define KB 32
#define PADE 40
#define TILEB (128*PADE*2)
#define STGB  (4*TILEB)
#define GEMM_SMEM (2*STGB)

__global__ void __launch_bounds__(256) gemm_mma(
    const __nv_bfloat16* __restrict__ Ap, const __nv_bfloat16* __restrict__ Bp,
    const float* __restrict__ bias, const float* __restrict__ resid,
    float* __restrict__ C, int M, int N, int K)
{
    extern __shared__ char sm[];
    const size_t MK = (size_t)M * K, NK = (size_t)N * K;
    int tid = threadIdx.x, lane = tid & 31, wid = tid >> 5;
    int wm = wid >> 2, wn = wid & 3;
    int bm = blockIdx.y * 128, bn = blockIdx.x * 128;
    uint32_t sbase = smem_u32(sm);

    float acc[4][4][4];
    #pragma unroll
    for (int i = 0; i < 4; i++)
        #pragma unroll
        for (int j = 0; j < 4; j++)
            #pragma unroll
            for (int q = 0; q < 4; q++) acc[i][j][q] = 0.f;

    int a_r = lane & 15, a_c = (lane & 16) ? 8 : 0;
    int b_r = ((lane >> 4) << 3) + (lane & 7), b_c = (lane & 8);
    const int KBn = K / KB;

    auto load_stage = [&](int kb, int stg) {
        #pragma unroll
        for (int t4 = 0; t4 < 4; t4++) {
            const __nv_bfloat16* base =
                (t4 < 2) ? (Ap + (t4 ? MK : 0)) : (Bp + (t4 == 3 ? NK : 0));
            int rowbase = (t4 < 2) ? bm : bn;
            #pragma unroll
            for (int i = 0; i < 2; i++) {
                int c = i * 256 + tid;
                int row = c >> 2, cc = c & 3;
                uint32_t dst = sbase + stg * STGB + t4 * TILEB
                             + (uint32_t)(row * (PADE * 2) + cc * 16);
                const __nv_bfloat16* src =
                    base + (size_t)(rowbase + row) * K + kb * KB + cc * 8;
                CPASYNC(dst, src);
            }
        }
    };

    load_stage(0, 0);
    CPCOMMIT();

    for (int kb = 0; kb < KBn; kb++) {
        if (kb + 1 < KBn) {
            load_stage(kb + 1, (kb + 1) & 1);
            CPCOMMIT();
            CPWAIT(1);
        } else {
            CPWAIT(0);
        }
        __syncthreads();

        uint32_t sa = sbase + (kb & 1) * STGB;
        #pragma unroll
        for (int term = 0; term < 3; term++) {
            uint32_t ao = sa + ((term == 2) ? TILEB : 0);
            uint32_t bo = sa + 2 * TILEB + ((term == 1) ? TILEB : 0);
            #pragma unroll
            for (int ks = 0; ks < KB; ks += 16) {
                uint32_t afr[4][4];
                #pragma unroll
                for (int mt = 0; mt < 4; mt++) {
                    uint32_t ad = ao + (uint32_t)(((wm * 64 + mt * 16 + a_r) * PADE
                                                   + ks + a_c) * 2);
                    LDSM4(afr[mt], ad);
                }
                uint32_t bfr[2][4];
                #pragma unroll
                for (int np = 0; np < 2; np++) {
                    uint32_t bd = bo + (uint32_t)(((wn * 32 + np * 16 + b_r) * PADE
                                                   + ks + b_c) * 2);
                    LDSM4(bfr[np], bd);
                }
                #pragma unroll
                for (int mt = 0; mt < 4; mt++)
                    #pragma unroll
                    for (int nt = 0; nt < 4; nt++)
                        MMA16816(acc[mt][nt], afr[mt],
                                 bfr[nt >> 1][(nt & 1) * 2],
                                 bfr[nt >> 1][(nt & 1) * 2 + 1]);
            }
        }
        __syncthreads();
    }

    int g = lane >> 2, t = lane & 3;
    #pragma unroll
    for (int mt = 0; mt < 4; mt++) {
        #pragma unroll
        for (int half = 0; half < 2; half++) {
            int row = bm + wm * 64 + mt * 16 + g + half * 8;
            float* cp = C + (size_t)row * N;
            const float* rp = resid ? (resid + (size_t)row * N) : nullptr;
            #pragma unroll
            for (int nt = 0; nt < 4; nt++) {
                int col = bn + wn * 32 + nt * 8 + t * 2;
                float2 v;
                v.x = acc[mt][nt][half * 2 + 0];
                v.y = acc[mt][nt][half * 2 + 1];
                if (bias) {
                    float2 b2v = *(const float2*)(bias + col);
                    v.x += b2v.x; v.y += b2v.y;
                }
                if (rp) {
                    float2 r2v = *(const float2*)(rp + col);
                    v.x += r2v.x; v.y += r2v.y;
                }
                *(float2*)(cp + col) = v;
            }
        }
    }
}

// ---------------- split K/V into per-head bf16 hi/lo layouts ------------------
// K out: [bh][t][64] (hi | lo at +BH*TT*HS) ; V out transposed: [bh][c][T]
__global__ void __launch_bounds__(256) split_kv(
    const float* __restrict__ QKV, __nv_bfloat16* __restrict__ KBo,
    __nv_bfloat16* __restrict__ VBo)
{
    __shared__ float vs[64][65];
    int tid = threadIdx.x;
    int tt = blockIdx.x, bh = blockIdx.y;
    int b = bh / HH, hh = bh % HH;
    const size_t LO = (size_t)BH * TT * HS;

    #pragma unroll
    for (int i = 0; i < 8; i++) {
        int p = i * 256 + tid;
        int row = p >> 5, c = (p & 31) * 2;
        const float* s = QKV + (size_t)(b * TT + tt * 64 + row) * QKVN + DD + hh * HS + c;
        __nv_bfloat16 h0, l0, h1, l1;
        split2(s[0], h0, l0); split2(s[1], h1, l1);
        size_t o = ((size_t)bh * TT + tt * 64 + row) * HS + c;
        *(uint32_t*)(KBo + o)      = packbf(h0, h1);
        *(uint32_t*)(KBo + LO + o) = packbf(l0, l1);
    }
    #pragma unroll
    for (int i = 0; i < 8; i++) {
        int p = i * 256 + tid;
        int row = p >> 5, c = (p & 31) * 2;
        const float* s = QKV + (size_t)(b * TT + tt * 64 + row) * QKVN + 2 * DD + hh * HS + c;
        vs[row][c] = s[0]; vs[row][c + 1] = s[1];
    }
    __syncthreads();
    #pragma unroll
    for (int i = 0; i < 8; i++) {
        int p = i * 256 + tid;
        int c = p >> 5, t2 = (p & 31) * 2;
        __nv_bfloat16 h0, l0, h1, l1;
        split2(vs[t2][c], h0, l0); split2(vs[t2 + 1][c], h1, l1);
        size_t o = ((size_t)bh * HS + c) * TT + tt * 64 + t2;
        *(uint32_t*)(VBo + o)      = packbf(h0, h1);
        *(uint32_t*)(VBo + LO + o) = packbf(l0, l1);
    }
}

// ---------------- tensor-core causal flash attention --------------------------
// CTA: 128 q-rows, 8 warps x 16 rows (each warp owns full 64-key stripe).
// ktile = 64 keys. QK^T: 3-term hi/lo split. PV: P bf16 x (Vhi + Vlo);
// l summed from bf16-rounded P (weights exactly normalized).
// smem: QH(18432) QL(18432) | 2 stages x [KH KL VH VL](9216 each), stride 72 elems.
#define ATT_STG 36864
#define ATT_SMEM (36864 + 2*ATT_STG)

__global__ void __launch_bounds__(256, 2) attn_tc(
    const float* __restrict__ QKV, const __nv_bfloat16* __restrict__ KBi,
    const __nv_bfloat16* __restrict__ VBi, __nv_bfloat16* __restrict__ ATB)
{
    extern __shared__ char sm[];
    uint32_t sbase = smem_u32(sm);
    int tid = threadIdx.x, lane = tid & 31, wid = tid >> 5;
    int qt = (int)(gridDim.x - 1 - blockIdx.x);   // longest blocks first
    int bh = blockIdx.y, b = bh / HH, hh = bh % HH;
    int q0 = qt * 128;
    const size_t LO = (size_t)BH * TT * HS;
    int nkt = 2 * qt + 2;

    int a_r = lane & 15, a_c = (lane & 16) ? 8 : 0;
    int b_r = ((lane >> 4) << 3) + (lane & 7), b_c = lane & 8;
    int g = lane >> 2, tq = lane & 3;

    auto ldkv = [&](int kt, int stg) {
        uint32_t sb2 = sbase + 36864 + stg * ATT_STG;
        size_t kbase = ((size_t)bh * TT + kt * 64) * HS;
        size_t vbase = (size_t)bh * HS * TT + kt * 64;
        #pragma unroll
        for (int i = 0; i < 8; i++) {
            int ch = i * 256 + tid;            // 0..2047
            int tile = ch >> 9;                // 0:KH 1:KL 2:VH 3:VL
            int r = (ch >> 3) & 63, cc = ch & 7;
            uint32_t dst = sb2 + tile * 9216 + r * 144 + cc * 16;
            const __nv_bfloat16* src;
            if (tile == 0)      src = KBi + kbase + r * 64 + cc * 8;
            else if (tile == 1) src = KBi + LO + kbase + r * 64 + cc * 8;
            else if (tile == 2) src = VBi + vbase + (size_t)r * TT + cc * 8;
            else                src = VBi + LO + vbase + (size_t)r * TT + cc * 8;
            CPASYNC(dst, src);
        }
    };

    ldkv(0, 0);
    CPCOMMIT();

    // stage Q: scale + split into QH/QL (stride 72 elems = 144 B)
    for (int p = tid; p < 4096; p += 256) {
        int row = p >> 5, c = (p & 31) * 2;
        const float* s = QKV + (size_t)(b * TT + q0 + row) * QKVN + hh * HS + c;
        __nv_bfloat16 h0, l0, h1, l1;
        split2(s[0] * SCL, h0, l0); split2(s[1] * SCL, h1, l1);
        *(uint32_t*)(sm + (row * 72 + c) * 2)         = packbf(h0, h1);
        *(uint32_t*)(sm + 18432 + (row * 72 + c) * 2) = packbf(l0, l1);
    }
    __syncthreads();

    float oacc[8][4];
    #pragma unroll
    for (int n = 0; n < 8; n++)
        #pragma unroll
        for (int j = 0; j < 4; j++) oacc[n][j] = 0.f;
    float lsum0 = 0.f, lsum1 = 0.f;

    for (int kt = 0; kt < nkt; kt++) {
        if (kt + 1 < nkt) { ldkv(kt + 1, (kt + 1) & 1); CPCOMMIT(); CPWAIT(1); }
        else              { CPWAIT(0); }
        __syncthreads();

        uint32_t KHb = sbase + 36864 + (kt & 1) * ATT_STG;
        uint32_t KLb = KHb + 9216, VHb = KHb + 18432, VLb = KHb + 27648;

        float sacc[8][4];
        #pragma unroll
        for (int n = 0; n < 8; n++)
            #pragma unroll
            for (int j = 0; j < 4; j++) sacc[n][j] = 0.f;

        // --- S = Q K^T, 3-term split ---
        #pragma unroll
        for (int ks = 0; ks < 4; ks++) {
            uint32_t qh[4], ql[4];
            uint32_t qa = sbase + (uint32_t)(((wid * 16 + a_r) * 72 + ks * 16 + a_c) * 2);
            LDSM4(qh, qa);
            LDSM4(ql, qa + 18432);
            #pragma unroll
            for (int nt2 = 0; nt2 < 4; nt2++) {
                uint32_t kf[4];
                uint32_t ka = (uint32_t)(((nt2 * 16 + b_r) * 72 + ks * 16 + b_c) * 2);
                LDSM4(kf, KHb + ka);
                MMA16816(sacc[2*nt2],     qh, kf[0], kf[1]);
                MMA16816(sacc[2*nt2 + 1], qh, kf[2], kf[3]);
                MMA16816(sacc[2*nt2],     ql, kf[0], kf[1]);
                MMA16816(sacc[2*nt2 + 1], ql, kf[2], kf[3]);
                LDSM4(kf, KLb + ka);
                MMA16816(sacc[2*nt2],     qh, kf[0], kf[1]);
                MMA16816(sacc[2*nt2 + 1], qh, kf[2], kf[3]);
            }
        }

        // --- softmax numerators: p = exp(s) with causal mask ---
        bool msk = (kt >= 2 * qt);
        int r0 = q0 + wid * 16 + g, r1 = r0 + 8;
        int cb = kt * 64 + tq * 2;
        #pragma unroll
        for (int n = 0; n < 8; n++) {
            #pragma unroll
            for (int j = 0; j < 4; j++) {
                int c = cb + n * 8 + (j & 1);
                int r = (j < 2) ? r0 : r1;
                sacc[n][j] = (!msk || c <= r) ? __expf(sacc[n][j]) : 0.f;
            }
        }

        // --- pack P (bf16), accumulate l from rounded P, PV MMAs ---
        #pragma unroll
        for (int pk = 0; pk < 4; pk++) {
            __nv_bfloat16 p00 = __float2bfloat16_rn(sacc[2*pk][0]);
            __nv_bfloat16 p01 = __float2bfloat16_rn(sacc[2*pk][1]);
            __nv_bfloat16 p02 = __float2bfloat16_rn(sacc[2*pk][2]);
            __nv_bfloat16 p03 = __float2bfloat16_rn(sacc[2*pk][3]);
            __nv_bfloat16 p10 = __float2bfloat16_rn(sacc[2*pk+1][0]);
            __nv_bfloat16 p11 = __float2bfloat16_rn(sacc[2*pk+1][1]);
            __nv_bfloat16 p12 = __float2bfloat16_rn(sacc[2*pk+1][2]);
            __nv_bfloat16 p13 = __float2bfloat16_rn(sacc[2*pk+1][3]);
            lsum0 += __bfloat162float(p00) + __bfloat162float(p01)
                   + __bfloat162float(p10) + __bfloat162float(p11);
            lsum1 += __bfloat162float(p02) + __bfloat162float(p03)
                   + __bfloat162float(p12) + __bfloat162float(p13);
            uint32_t pa[4];
            pa[0] = packbf(p00, p01);
            pa[1] = packbf(p02, p03);
            pa[2] = packbf(p10, p11);
            pa[3] = packbf(p12, p13);
            #pragma unroll
            for (int nt2 = 0; nt2 < 4; nt2++) {
                uint32_t vf[4];
                uint32_t va = (uint32_t)(((nt2 * 16 + b_r) * 72 + pk * 16 + b_c) * 2);
                LDSM4(vf, VHb + va);
                MMA16816(oacc[2*nt2],     pa, vf[0], vf[1]);
                MMA16816(oacc[2*nt2 + 1], pa, vf[2], vf[3]);
                LDSM4(vf, VLb + va);
                MMA16816(oacc[2*nt2],     pa, vf[0], vf[1]);
                MMA16816(oacc[2*nt2 + 1], pa, vf[2], vf[3]);
            }
        }
        __syncthreads();
    }

    // reduce l across the 4 lanes sharing a row
    lsum0 += __shfl_xor_sync(0xffffffffu, lsum0, 1);
    lsum0 += __shfl_xor_sync(0xffffffffu, lsum0, 2);
    lsum1 += __shfl_xor_sync(0xffffffffu, lsum1, 1);
    lsum1 += __shfl_xor_sync(0xffffffffu, lsum1, 2);
    float inv0 = 1.0f / lsum0, inv1 = 1.0f / lsum1;

    // write O as bf16 hi/lo split into g_atb [NT][DD]
    const size_t LOA = (size_t)NT * DD;
    size_t rg0 = (size_t)(b * TT + q0 + wid * 16 + g);
    size_t rg1 = rg0 + 8;
    int lc = hh * HS + tq * 2;
    #pragma unroll
    for (int n = 0; n < 8; n++) {
        __nv_bfloat16 h0, l0, h1, l1;
        split2(oacc[n][0] * inv0, h0, l0);
        split2(oacc[n][1] * inv0, h1, l1);
        *(uint32_t*)(ATB + rg0 * DD + lc + n * 8)       = packbf(h0, h1);
        *(uint32_t*)(ATB + LOA + rg0 * DD + lc + n * 8) = packbf(l0, l1);
        split2(oacc[n][2] * inv1, h0, l0);
        split2(oacc[n][3] * inv1, h1, l1);
        *(uint32_t*)(ATB + rg1 * DD + lc + n * 8)       = packbf(h0, h1);
        *(uint32_t*)(ATB + LOA + rg1 * DD + lc + n * 8) = packbf(l0, l1);
    }
}

// ---------------- RMSNorm -> bf16 hi/lo --------------------------------------
__global__ void __launch_bounds__(256) rmsnorm_split(
    const float* __restrict__ x, const float* __restrict__ gw,
    __nv_bfloat16* __restrict__ o)
{
    int row = blockIdx.x;
    const float* xr = x + (size_t)row * DD;
    int tid = threadIdx.x;
    float ss = 0.f;
    for (int i = tid; i < DD; i += 256) { float v = xr[i]; ss += v * v; }
    #pragma unroll
    for (int o2 = 16; o2 > 0; o2 >>= 1) ss += __shfl_xor_sync(0xffffffffu, ss, o2);
    __shared__ float red[8];
    if ((tid & 31) == 0) red[tid >> 5] = ss;
    __syncthreads();
    if (tid < 8) {
        float v = red[tid];
        #pragma unroll
        for (int o2 = 4; o2 > 0; o2 >>= 1) v += __shfl_xor_sync(0xffu, v, o2);
        if (tid == 0) red[0] = v;
    }
    __syncthreads();
    float rms = sqrtf(red[0] * (1.0f / DD));
    float inv = 1.0f / (rms + 1e-8f);
    const size_t LOA = (size_t)NT * DD;
    for (int i = tid; i < DD; i += 256) {
        float v = gw[i] * xr[i] * inv;
        __nv_bfloat16 h, l; split2(v, h, l);
        o[(size_t)row * DD + i] = h;
        o[LOA + (size_t)row * DD + i] = l;
    }
}

// ---------------- SwiGLU -> bf16 hi/lo ---------------------------------------
__global__ void __launch_bounds__(256) swiglu_split(
    const float* __restrict__ u, __nv_bfloat16* __restrict__ out)
{
    int idx = blockIdx.x * 256 + threadIdx.x;
    if (idx >= NT * HALF) return;
    int m = idx / HALF, j = idx - m * HALF;
    float a  = u[(size_t)m * FF + j];
    float gt = u[(size_t)m * FF + HALF + j];
    float s  = gt / (1.0f + __expf(-gt));
    __nv_bfloat16 h, l; split2(s * a, h, l);
    out[idx] = h;
    out[(size_t)NT * HALF + idx] = l;
}

// ---------------- launch -----------------------------------------------------
extern "C" void kernel_launch(void* const* d_in, const int* in_sizes, int n_in,
                              void* d_out, int out_size)
{
    const float* x  = (const float*)d_in[0];
    const float* Wq = (const float*)d_in[1];
    const float* Wk = (const float*)d_in[2];
    const float* Wv = (const float*)d_in[3];
    const float* Wo = (const float*)d_in[4];
    const float* bo = (const float*)d_in[5];
    const float* W1 = (const float*)d_in[6];
    const float* b1 = (const float*)d_in[7];
    const float* W2 = (const float*)d_in[8];
    const float* b2 = (const float*)d_in[9];
    const float* g1 = (const float*)d_in[10];
    const float* g2 = (const float*)d_in[11];
    float* out = (float*)d_out;

    float *qkv, *x1, *u;
    __nv_bfloat16 *ah, *atb, *h2b, *swb, *kb, *vb, *bqkv, *bo_, *b1_, *b2_;
    cudaGetSymbolAddress((void**)&qkv, g_qkv);
    cudaGetSymbolAddress((void**)&x1,  g_x1);
    cudaGetSymbolAddress((void**)&u,   g_u);
    cudaGetSymbolAddress((void**)&ah,  g_ah);
    cudaGetSymbolAddress((void**)&atb, g_atb);
    cudaGetSymbolAddress((void**)&h2b, g_h2b);
    cudaGetSymbolAddress((void**)&swb, g_swb);
    cudaGetSymbolAddress((void**)&kb,  g_kb);
    cudaGetSymbolAddress((void**)&vb,  g_vb);
    cudaGetSymbolAddress((void**)&bqkv, g_bqkv);
    cudaGetSymbolAddress((void**)&bo_,  g_bo);
    cudaGetSymbolAddress((void**)&b1_,  g_b1);
    cudaGetSymbolAddress((void**)&b2_,  g_b2);

    cudaFuncSetAttribute(gemm_mma, cudaFuncAttributeMaxDynamicSharedMemorySize, GEMM_SMEM);
    cudaFuncSetAttribute(attn_tc,  cudaFuncAttributeMaxDynamicSharedMemorySize, ATT_SMEM);

    const size_t QNK = (size_t)QKVN * DD;

    // launches 0-3: weight prep for QKV + Wo (launch #5 = gemm_mma for ncu)
    int gp = (DD * (DD / 4) + 255) / 256;
    prep_b<<<gp, 256>>>(Wq, bqkv,                   bqkv + QNK,                   DD, DD, 1, 0);
    prep_b<<<gp, 256>>>(Wk, bqkv + (size_t)DD*DD,   bqkv + QNK + (size_t)DD*DD,   DD, DD, 1, 0);
    prep_b<<<gp, 256>>>(Wv, bqkv + (size_t)2*DD*DD, bqkv + QNK + (size_t)2*DD*DD, DD, DD, 1, 0);
    prep_b<<<gp, 256>>>(Wo, bo_, bo_ + (size_t)DD*DD, DD, DD, 0, DD);

    // 4) ah = split(rmsnorm(x, g1))
    rmsnorm_split<<<NT, 256>>>(x, g1, ah);

    // 5) qkv = ah @ [Wq|Wk|Wv]
    gemm_mma<<<dim3(QKVN / 128, NT / 128), 256, GEMM_SMEM>>>(
        ah, bqkv, nullptr, nullptr, qkv, NT, QKVN, DD);

    // 6) split K/V into per-head hi/lo layouts
    split_kv<<<dim3(TT / 64, BH), 256>>>(qkv, kb, vb);

    // 7) tensor-core attention -> atb (split)
    attn_tc<<<dim3(TT / 128, BH), 256, ATT_SMEM>>>(qkv, kb, vb, atb);

    // 8) x1 = x + atb @ Wo + bo
    gemm_mma<<<dim3(DD / 128, NT / 128), 256, GEMM_SMEM>>>(
        atb, bo_, bo, x, x1, NT, DD, DD);

    // 9) h2b = split(rmsnorm(x1, g2))
    rmsnorm_split<<<NT, 256>>>(x1, g2, h2b);

    // 10) prep W1, 11) u = h2b @ W1 + b1
    prep_b<<<(FF * (DD / 4) + 255) / 256, 256>>>(W1, b1_, b1_ + (size_t)FF*DD, FF, DD, 0, FF);
    gemm_mma<<<dim3(FF / 128, NT / 128), 256, GEMM_SMEM>>>(
        h2b, b1_, b1, nullptr, u, NT, FF, DD);

    // 12) swb = split(swiglu(u))
    swiglu_split<<<(NT * HALF + 255) / 256, 256>>>(u, swb);

    // 13) prep W2, 14) out = x1 + swb @ W2 + b2
    prep_b<<<(DD * (HALF / 4) + 255) / 256, 256>>>(W2, b2_, b2_ + (size_t)DD*HALF, DD, HALF, 0, DD);
    gemm_mma<<<dim3(DD / 128, NT / 128), 256, GEMM_SMEM>>>(
        swb, b2_, b2, x1, out, NT, DD, HALF);
}

// round 5
// speedup vs baseline: 3.2533x; 1.7453x over previous
#include <cuda_runtime.h>
#include <cuda_bf16.h>
#include <cstdint>
#include <cstddef>

// Problem constants
#define BB 2
#define TT 2048
#define DD 768
#define HH 12
#define HS 64
#define FF 3072
#define HALF 1536
#define NT (BB*TT)       // 4096
#define QKVN 2304        // fused q|k|v output width
#define BH 24            // B*H
#define SCL 0.03608439182435161f   // 768^-0.5

// ---------------- scratch (device globals) -----------------------------------
__device__ float g_qkv[(size_t)NT*QKVN];
__device__ float g_x1 [(size_t)NT*DD];
__device__ float g_u  [(size_t)NT*FF];
// activation splits: hi block then lo block
__device__ __nv_bfloat16 g_ah [(size_t)2*NT*DD];    // rmsnorm1 out
__device__ __nv_bfloat16 g_atb[(size_t)2*NT*DD];    // attention out
__device__ __nv_bfloat16 g_h2b[(size_t)2*NT*DD];    // rmsnorm2 out
__device__ __nv_bfloat16 g_swb[(size_t)2*NT*HALF];  // swiglu out
// per-head K/V splits: K [bh][t][64] hi|lo ; V transposed [bh][c][T] hi|lo
__device__ __nv_bfloat16 g_kb [(size_t)2*BH*TT*HS];
__device__ __nv_bfloat16 g_vb [(size_t)2*BH*TT*HS];
// weight splits: hi block [N*K] then lo block [N*K], layout [N][K]
__device__ __nv_bfloat16 g_bqkv[(size_t)2*QKVN*DD];
__device__ __nv_bfloat16 g_bo  [(size_t)2*DD*DD];
__device__ __nv_bfloat16 g_b1  [(size_t)2*FF*DD];
__device__ __nv_bfloat16 g_b2  [(size_t)2*DD*HALF];

// ---------------- helpers ----------------------------------------------------
__device__ __forceinline__ uint32_t smem_u32(const void* p) {
    uint32_t a;
    asm("{ .reg .u64 t; cvta.to.shared.u64 t, %1; cvt.u32.u64 %0, t; }" : "=r"(a) : "l"(p));
    return a;
}
#define CPASYNC(d, s) asm volatile("cp.async.cg.shared.global [%0], [%1], 16;" :: "r"(d), "l"(s) : "memory")
#define CPCOMMIT()    asm volatile("cp.async.commit_group;" ::: "memory")
#define CPWAIT(n)     asm volatile("cp.async.wait_group %0;" :: "n"(n) : "memory")
#define LDSM4(r, a)                                                              \
    asm volatile("ldmatrix.sync.aligned.m8n8.x4.shared.b16 {%0,%1,%2,%3}, [%4];" \
        : "=r"((r)[0]), "=r"((r)[1]), "=r"((r)[2]), "=r"((r)[3]) : "r"(a))
#define MMA16816(c, a, b0, b1)                                                   \
    asm volatile("mma.sync.aligned.m16n8k16.row.col.f32.bf16.bf16.f32 "          \
        "{%0,%1,%2,%3}, {%4,%5,%6,%7}, {%8,%9}, {%0,%1,%2,%3};"                  \
        : "+f"((c)[0]), "+f"((c)[1]), "+f"((c)[2]), "+f"((c)[3])                 \
        : "r"((a)[0]), "r"((a)[1]), "r"((a)[2]), "r"((a)[3]), "r"(b0), "r"(b1))

__device__ __forceinline__ void split2(float v, __nv_bfloat16& h, __nv_bfloat16& l) {
    h = __float2bfloat16_rn(v);
    l = __float2bfloat16_rn(v - __bfloat162float(h));
}
__device__ __forceinline__ uint32_t packbf(__nv_bfloat16 lo, __nv_bfloat16 hi) {
    return (uint32_t)__bfloat16_as_ushort(lo) | ((uint32_t)__bfloat16_as_ushort(hi) << 16);
}

// ---------------- fused weight prep (single launch) ---------------------------
// transpose/split all 6 weight matrices into [N][K] bf16 hi/lo
#define CQ (768*192)
#define CO (768*192)
#define C1 (3072*192)
#define C2 (768*384)

__global__ void __launch_bounds__(256) prep_all(
    const float* __restrict__ Wq, const float* __restrict__ Wk,
    const float* __restrict__ Wv, const float* __restrict__ Wo,
    const float* __restrict__ W1, const float* __restrict__ W2,
    __nv_bfloat16* __restrict__ bqkv, __nv_bfloat16* __restrict__ bo,
    __nv_bfloat16* __restrict__ b1,  __nv_bfloat16* __restrict__ b2)
{
    int idx = blockIdx.x * 256 + threadIdx.x;
    const float* W; __nv_bfloat16 *hi, *lo;
    int N, K, mode, srcLd, local;
    if (idx < 3 * CQ) {
        int m = idx / CQ; local = idx - m * CQ;
        W = (m == 0) ? Wq : (m == 1) ? Wk : Wv;
        hi = bqkv + (size_t)m * 768 * 768;
        lo = bqkv + (size_t)QKVN * DD + (size_t)m * 768 * 768;
        N = 768; K = 768; mode = 1; srcLd = 0;
    } else if (idx < 3 * CQ + CO) {
        local = idx - 3 * CQ; W = Wo;
        hi = bo; lo = bo + (size_t)768 * 768;
        N = 768; K = 768; mode = 0; srcLd = 768;
    } else if (idx < 3 * CQ + CO + C1) {
        local = idx - 3 * CQ - CO; W = W1;
        hi = b1; lo = b1 + (size_t)3072 * 768;
        N = 3072; K = 768; mode = 0; srcLd = 3072;
    } else {
        local = idx - 3 * CQ - CO - C1; W = W2;
        hi = b2; lo = b2 + (size_t)768 * 1536;
        N = 768; K = 1536; mode = 0; srcLd = 768;
    }
    int kq = K >> 2;
    int n = local / kq, k = (local - n * kq) << 2;
    union { __nv_bfloat16 b[4]; uint2 u; } H, L;
    #pragma unroll
    for (int j = 0; j < 4; j++) {
        size_t sa = (mode == 0)
            ? (size_t)(k + j) * srcLd + n
            : (size_t)(n >> 6) * ((size_t)K * 64) + (size_t)(k + j) * 64 + (n & 63);
        split2(W[sa], H.b[j], L.b[j]);
    }
    *(uint2*)(hi + (size_t)n * K + k) = H.u;
    *(uint2*)(lo + (size_t)n * K + k) = L.u;
}
#define PREP_GRID ((3*CQ + CO + C1 + C2) / 256)   // 5760

// ---------------- mma.sync bf16-split GEMM -----------------------------------
// CTA 128x128, warp 64x32, K-block 32, 2-stage cp.async, fragment-reuse inner loop.
#define KB 32
#define PADE 40
#define TILEB (128*PADE*2)
#define STGB  (4*TILEB)
#define GEMM_SMEM (2*STGB)

__global__ void __launch_bounds__(256, 2) gemm_mma(
    const __nv_bfloat16* __restrict__ Ap, const __nv_bfloat16* __restrict__ Bp,
    const float* __restrict__ bias, const float* __restrict__ resid,
    float* __restrict__ C, int M, int N, int K)
{
    extern __shared__ char sm[];
    const size_t MK = (size_t)M * K, NK = (size_t)N * K;
    int tid = threadIdx.x, lane = tid & 31, wid = tid >> 5;
    int wm = wid >> 2, wn = wid & 3;
    int bm = blockIdx.y * 128, bn = blockIdx.x * 128;
    uint32_t sbase = smem_u32(sm);

    float acc[4][4][4];
    #pragma unroll
    for (int i = 0; i < 4; i++)
        #pragma unroll
        for (int j = 0; j < 4; j++)
            #pragma unroll
            for (int q = 0; q < 4; q++) acc[i][j][q] = 0.f;

    int a_r = lane & 15, a_c = (lane & 16) ? 8 : 0;
    int b_r = ((lane >> 4) << 3) + (lane & 7), b_c = (lane & 8);
    const int KBn = K / KB;

    auto load_stage = [&](int kb, int stg) {
        #pragma unroll
        for (int t4 = 0; t4 < 4; t4++) {
            const __nv_bfloat16* base =
                (t4 < 2) ? (Ap + (t4 ? MK : 0)) : (Bp + (t4 == 3 ? NK : 0));
            int rowbase = (t4 < 2) ? bm : bn;
            #pragma unroll
            for (int i = 0; i < 2; i++) {
                int c = i * 256 + tid;
                int row = c >> 2, cc = c & 3;
                uint32_t dst = sbase + stg * STGB + t4 * TILEB
                             + (uint32_t)(row * (PADE * 2) + cc * 16);
                const __nv_bfloat16* src =
                    base + (size_t)(rowbase + row) * K + kb * KB + cc * 8;
                CPASYNC(dst, src);
            }
        }
    };

    load_stage(0, 0);
    CPCOMMIT();

    for (int kb = 0; kb < KBn; kb++) {
        if (kb + 1 < KBn) {
            load_stage(kb + 1, (kb + 1) & 1);
            CPCOMMIT();
            CPWAIT(1);
        } else {
            CPWAIT(0);
        }
        __syncthreads();

        uint32_t sa = sbase + (kb & 1) * STGB;
        uint32_t aoh = sa, aol = sa + TILEB, boh = sa + 2 * TILEB, bol = sa + 3 * TILEB;
        #pragma unroll
        for (int ks = 0; ks < KB; ks += 16) {
            uint32_t ah[4][4], al[4][4], bf2[2][4];
            #pragma unroll
            for (int mt = 0; mt < 4; mt++) {
                uint32_t off = (uint32_t)(((wm * 64 + mt * 16 + a_r) * PADE + ks + a_c) * 2);
                LDSM4(ah[mt], aoh + off);
                LDSM4(al[mt], aol + off);
            }
            #pragma unroll
            for (int np = 0; np < 2; np++) {
                uint32_t off = (uint32_t)(((wn * 32 + np * 16 + b_r) * PADE + ks + b_c) * 2);
                LDSM4(bf2[np], boh + off);
            }
            // term hh
            #pragma unroll
            for (int mt = 0; mt < 4; mt++)
                #pragma unroll
                for (int nt = 0; nt < 4; nt++)
                    MMA16816(acc[mt][nt], ah[mt],
                             bf2[nt >> 1][(nt & 1) * 2], bf2[nt >> 1][(nt & 1) * 2 + 1]);
            // term lh
            #pragma unroll
            for (int mt = 0; mt < 4; mt++)
                #pragma unroll
                for (int nt = 0; nt < 4; nt++)
                    MMA16816(acc[mt][nt], al[mt],
                             bf2[nt >> 1][(nt & 1) * 2], bf2[nt >> 1][(nt & 1) * 2 + 1]);
            // reload B regs with lo, term hl
            #pragma unroll
            for (int np = 0; np < 2; np++) {
                uint32_t off = (uint32_t)(((wn * 32 + np * 16 + b_r) * PADE + ks + b_c) * 2);
                LDSM4(bf2[np], bol + off);
            }
            #pragma unroll
            for (int mt = 0; mt < 4; mt++)
                #pragma unroll
                for (int nt = 0; nt < 4; nt++)
                    MMA16816(acc[mt][nt], ah[mt],
                             bf2[nt >> 1][(nt & 1) * 2], bf2[nt >> 1][(nt & 1) * 2 + 1]);
        }
        __syncthreads();
    }

    int g = lane >> 2, t = lane & 3;
    #pragma unroll
    for (int mt = 0; mt < 4; mt++) {
        #pragma unroll
        for (int half = 0; half < 2; half++) {
            int row = bm + wm * 64 + mt * 16 + g + half * 8;
            float* cp = C + (size_t)row * N;
            const float* rp = resid ? (resid + (size_t)row * N) : nullptr;
            #pragma unroll
            for (int nt = 0; nt < 4; nt++) {
                int col = bn + wn * 32 + nt * 8 + t * 2;
                float2 v;
                v.x = acc[mt][nt][half * 2 + 0];
                v.y = acc[mt][nt][half * 2 + 1];
                if (bias) {
                    float2 b2v = *(const float2*)(bias + col);
                    v.x += b2v.x; v.y += b2v.y;
                }
                if (rp) {
                    float2 r2v = *(const float2*)(rp + col);
                    v.x += r2v.x; v.y += r2v.y;
                }
                *(float2*)(cp + col) = v;
            }
        }
    }
}

// ---------------- split K/V into per-head bf16 hi/lo layouts ------------------
__global__ void __launch_bounds__(256) split_kv(
    const float* __restrict__ QKV, __nv_bfloat16* __restrict__ KBo,
    __nv_bfloat16* __restrict__ VBo)
{
    __shared__ float vs[64][65];
    int tid = threadIdx.x;
    int tt = blockIdx.x, bh = blockIdx.y;
    int b = bh / HH, hh = bh % HH;
    const size_t LO = (size_t)BH * TT * HS;

    #pragma unroll
    for (int i = 0; i < 8; i++) {
        int p = i * 256 + tid;
        int row = p >> 5, c = (p & 31) * 2;
        const float* s = QKV + (size_t)(b * TT + tt * 64 + row) * QKVN + DD + hh * HS + c;
        __nv_bfloat16 h0, l0, h1, l1;
        split2(s[0], h0, l0); split2(s[1], h1, l1);
        size_t o = ((size_t)bh * TT + tt * 64 + row) * HS + c;
        *(uint32_t*)(KBo + o)      = packbf(h0, h1);
        *(uint32_t*)(KBo + LO + o) = packbf(l0, l1);
    }
    #pragma unroll
    for (int i = 0; i < 8; i++) {
        int p = i * 256 + tid;
        int row = p >> 5, c = (p & 31) * 2;
        const float* s = QKV + (size_t)(b * TT + tt * 64 + row) * QKVN + 2 * DD + hh * HS + c;
        vs[row][c] = s[0]; vs[row][c + 1] = s[1];
    }
    __syncthreads();
    #pragma unroll
    for (int i = 0; i < 8; i++) {
        int p = i * 256 + tid;
        int c = p >> 5, t2 = (p & 31) * 2;
        __nv_bfloat16 h0, l0, h1, l1;
        split2(vs[t2][c], h0, l0); split2(vs[t2 + 1][c], h1, l1);
        size_t o = ((size_t)bh * HS + c) * TT + tt * 64 + t2;
        *(uint32_t*)(VBo + o)      = packbf(h0, h1);
        *(uint32_t*)(VBo + LO + o) = packbf(l0, l1);
    }
}

// ---------------- tensor-core causal flash attention --------------------------
#define ATT_STG 36864
#define ATT_SMEM (36864 + 2*ATT_STG)

__global__ void __launch_bounds__(256, 2) attn_tc(
    const float* __restrict__ QKV, const __nv_bfloat16* __restrict__ KBi,
    const __nv_bfloat16* __restrict__ VBi, __nv_bfloat16* __restrict__ ATB)
{
    extern __shared__ char sm[];
    uint32_t sbase = smem_u32(sm);
    int tid = threadIdx.x, lane = tid & 31, wid = tid >> 5;
    int qt = (int)(gridDim.x - 1 - blockIdx.x);
    int bh = blockIdx.y, b = bh / HH, hh = bh % HH;
    int q0 = qt * 128;
    const size_t LO = (size_t)BH * TT * HS;
    int nkt = 2 * qt + 2;

    int a_r = lane & 15, a_c = (lane & 16) ? 8 : 0;
    int b_r = ((lane >> 4) << 3) + (lane & 7), b_c = lane & 8;
    int g = lane >> 2, tq = lane & 3;

    auto ldkv = [&](int kt, int stg) {
        uint32_t sb2 = sbase + 36864 + stg * ATT_STG;
        size_t kbase = ((size_t)bh * TT + kt * 64) * HS;
        size_t vbase = (size_t)bh * HS * TT + kt * 64;
        #pragma unroll
        for (int i = 0; i < 8; i++) {
            int ch = i * 256 + tid;
            int tile = ch >> 9;
            int r = (ch >> 3) & 63, cc = ch & 7;
            uint32_t dst = sb2 + tile * 9216 + r * 144 + cc * 16;
            const __nv_bfloat16* src;
            if (tile == 0)      src = KBi + kbase + r * 64 + cc * 8;
            else if (tile == 1) src = KBi + LO + kbase + r * 64 + cc * 8;
            else if (tile == 2) src = VBi + vbase + (size_t)r * TT + cc * 8;
            else                src = VBi + LO + vbase + (size_t)r * TT + cc * 8;
            CPASYNC(dst, src);
        }
    };

    ldkv(0, 0);
    CPCOMMIT();

    for (int p = tid; p < 4096; p += 256) {
        int row = p >> 5, c = (p & 31) * 2;
        const float* s = QKV + (size_t)(b * TT + q0 + row) * QKVN + hh * HS + c;
        __nv_bfloat16 h0, l0, h1, l1;
        split2(s[0] * SCL, h0, l0); split2(s[1] * SCL, h1, l1);
        *(uint32_t*)(sm + (row * 72 + c) * 2)         = packbf(h0, h1);
        *(uint32_t*)(sm + 18432 + (row * 72 + c) * 2) = packbf(l0, l1);
    }
    __syncthreads();

    float oacc[8][4];
    #pragma unroll
    for (int n = 0; n < 8; n++)
        #pragma unroll
        for (int j = 0; j < 4; j++) oacc[n][j] = 0.f;
    float lsum0 = 0.f, lsum1 = 0.f;

    for (int kt = 0; kt < nkt; kt++) {
        if (kt + 1 < nkt) { ldkv(kt + 1, (kt + 1) & 1); CPCOMMIT(); CPWAIT(1); }
        else              { CPWAIT(0); }
        __syncthreads();

        uint32_t KHb = sbase + 36864 + (kt & 1) * ATT_STG;
        uint32_t KLb = KHb + 9216, VHb = KHb + 18432, VLb = KHb + 27648;

        float sacc[8][4];
        #pragma unroll
        for (int n = 0; n < 8; n++)
            #pragma unroll
            for (int j = 0; j < 4; j++) sacc[n][j] = 0.f;

        #pragma unroll
        for (int ks = 0; ks < 4; ks++) {
            uint32_t qh[4], ql[4];
            uint32_t qa = sbase + (uint32_t)(((wid * 16 + a_r) * 72 + ks * 16 + a_c) * 2);
            LDSM4(qh, qa);
            LDSM4(ql, qa + 18432);
            #pragma unroll
            for (int nt2 = 0; nt2 < 4; nt2++) {
                uint32_t kf[4];
                uint32_t ka = (uint32_t)(((nt2 * 16 + b_r) * 72 + ks * 16 + b_c) * 2);
                LDSM4(kf, KHb + ka);
                MMA16816(sacc[2*nt2],     qh, kf[0], kf[1]);
                MMA16816(sacc[2*nt2 + 1], qh, kf[2], kf[3]);
                MMA16816(sacc[2*nt2],     ql, kf[0], kf[1]);
                MMA16816(sacc[2*nt2 + 1], ql, kf[2], kf[3]);
                LDSM4(kf, KLb + ka);
                MMA16816(sacc[2*nt2],     qh, kf[0], kf[1]);
                MMA16816(sacc[2*nt2 + 1], qh, kf[2], kf[3]);
            }
        }

        bool msk = (kt >= 2 * qt);
        int r0 = q0 + wid * 16 + g, r1 = r0 + 8;
        int cb = kt * 64 + tq * 2;
        #pragma unroll
        for (int n = 0; n < 8; n++) {
            #pragma unroll
            for (int j = 0; j < 4; j++) {
                int c = cb + n * 8 + (j & 1);
                int r = (j < 2) ? r0 : r1;
                sacc[n][j] = (!msk || c <= r) ? __expf(sacc[n][j]) : 0.f;
            }
        }

        #pragma unroll
        for (int pk = 0; pk < 4; pk++) {
            __nv_bfloat16 p00 = __float2bfloat16_rn(sacc[2*pk][0]);
            __nv_bfloat16 p01 = __float2bfloat16_rn(sacc[2*pk][1]);
            __nv_bfloat16 p02 = __float2bfloat16_rn(sacc[2*pk][2]);
            __nv_bfloat16 p03 = __float2bfloat16_rn(sacc[2*pk][3]);
            __nv_bfloat16 p10 = __float2bfloat16_rn(sacc[2*pk+1][0]);
            __nv_bfloat16 p11 = __float2bfloat16_rn(sacc[2*pk+1][1]);
            __nv_bfloat16 p12 = __float2bfloat16_rn(sacc[2*pk+1][2]);
            __nv_bfloat16 p13 = __float2bfloat16_rn(sacc[2*pk+1][3]);
            lsum0 += __bfloat162float(p00) + __bfloat162float(p01)
                   + __bfloat162float(p10) + __bfloat162float(p11);
            lsum1 += __bfloat162float(p02) + __bfloat162float(p03)
                   + __bfloat162float(p12) + __bfloat162float(p13);
            uint32_t pa[4];
            pa[0] = packbf(p00, p01);
            pa[1] = packbf(p02, p03);
            pa[2] = packbf(p10, p11);
            pa[3] = packbf(p12, p13);
            #pragma unroll
            for (int nt2 = 0; nt2 < 4; nt2++) {
                uint32_t vf[4];
                uint32_t va = (uint32_t)(((nt2 * 16 + b_r) * 72 + pk * 16 + b_c) * 2);
                LDSM4(vf, VHb + va);
                MMA16816(oacc[2*nt2],     pa, vf[0], vf[1]);
                MMA16816(oacc[2*nt2 + 1], pa, vf[2], vf[3]);
                LDSM4(vf, VLb + va);
                MMA16816(oacc[2*nt2],     pa, vf[0], vf[1]);
                MMA16816(oacc[2*nt2 + 1], pa, vf[2], vf[3]);
            }
        }
        __syncthreads();
    }

    lsum0 += __shfl_xor_sync(0xffffffffu, lsum0, 1);
    lsum0 += __shfl_xor_sync(0xffffffffu, lsum0, 2);
    lsum1 += __shfl_xor_sync(0xffffffffu, lsum1, 1);
    lsum1 += __shfl_xor_sync(0xffffffffu, lsum1, 2);
    float inv0 = 1.0f / lsum0, inv1 = 1.0f / lsum1;

    const size_t LOA = (size_t)NT * DD;
    size_t rg0 = (size_t)(b * TT + q0 + wid * 16 + g);
    size_t rg1 = rg0 + 8;
    int lc = hh * HS + tq * 2;
    #pragma unroll
    for (int n = 0; n < 8; n++) {
        __nv_bfloat16 h0, l0, h1, l1;
        split2(oacc[n][0] * inv0, h0, l0);
        split2(oacc[n][1] * inv0, h1, l1);
        *(uint32_t*)(ATB + rg0 * DD + lc + n * 8)       = packbf(h0, h1);
        *(uint32_t*)(ATB + LOA + rg0 * DD + lc + n * 8) = packbf(l0, l1);
        split2(oacc[n][2] * inv1, h0, l0);
        split2(oacc[n][3] * inv1, h1, l1);
        *(uint32_t*)(ATB + rg1 * DD + lc + n * 8)       = packbf(h0, h1);
        *(uint32_t*)(ATB + LOA + rg1 * DD + lc + n * 8) = packbf(l0, l1);
    }
}

// ---------------- RMSNorm -> bf16 hi/lo --------------------------------------
__global__ void __launch_bounds__(256) rmsnorm_split(
    const float* __restrict__ x, const float* __restrict__ gw,
    __nv_bfloat16* __restrict__ o)
{
    int row = blockIdx.x;
    const float* xr = x + (size_t)row * DD;
    int tid = threadIdx.x;
    float ss = 0.f;
    for (int i = tid; i < DD; i += 256) { float v = xr[i]; ss += v * v; }
    #pragma unroll
    for (int o2 = 16; o2 > 0; o2 >>= 1) ss += __shfl_xor_sync(0xffffffffu, ss, o2);
    __shared__ float red[8];
    if ((tid & 31) == 0) red[tid >> 5] = ss;
    __syncthreads();
    if (tid < 8) {
        float v = red[tid];
        #pragma unroll
        for (int o2 = 4; o2 > 0; o2 >>= 1) v += __shfl_xor_sync(0xffu, v, o2);
        if (tid == 0) red[0] = v;
    }
    __syncthreads();
    float rms = sqrtf(red[0] * (1.0f / DD));
    float inv = 1.0f / (rms + 1e-8f);
    const size_t LOA = (size_t)NT * DD;
    for (int i = tid; i < DD; i += 256) {
        float v = gw[i] * xr[i] * inv;
        __nv_bfloat16 h, l; split2(v, h, l);
        o[(size_t)row * DD + i] = h;
        o[LOA + (size_t)row * DD + i] = l;
    }
}

// ---------------- SwiGLU -> bf16 hi/lo ---------------------------------------
__global__ void __launch_bounds__(256) swiglu_split(
    const float* __restrict__ u, __nv_bfloat16* __restrict__ out)
{
    int idx = blockIdx.x * 256 + threadIdx.x;
    if (idx >= NT * HALF) return;
    int m = idx / HALF, j = idx - m * HALF;
    float a  = u[(size_t)m * FF + j];
    float gt = u[(size_t)m * FF + HALF + j];
    float s  = gt / (1.0f + __expf(-gt));
    __nv_bfloat16 h, l; split2(s * a, h, l);
    out[idx] = h;
    out[(size_t)NT * HALF + idx] = l;
}

// ---------------- launch -----------------------------------------------------
extern "C" void kernel_launch(void* const* d_in, const int* in_sizes, int n_in,
                              void* d_out, int out_size)
{
    const float* x  = (const float*)d_in[0];
    const float* Wq = (const float*)d_in[1];
    const float* Wk = (const float*)d_in[2];
    const float* Wv = (const float*)d_in[3];
    const float* Wo = (const float*)d_in[4];
    const float* bo = (const float*)d_in[5];
    const float* W1 = (const float*)d_in[6];
    const float* b1 = (const float*)d_in[7];
    const float* W2 = (const float*)d_in[8];
    const float* b2 = (const float*)d_in[9];
    const float* g1 = (const float*)d_in[10];
    const float* g2 = (const float*)d_in[11];
    float* out = (float*)d_out;

    float *qkv, *x1, *u;
    __nv_bfloat16 *ah, *atb, *h2b, *swb, *kb, *vb, *bqkv, *bo_, *b1_, *b2_;
    cudaGetSymbolAddress((void**)&qkv, g_qkv);
    cudaGetSymbolAddress((void**)&x1,  g_x1);
    cudaGetSymbolAddress((void**)&u,   g_u);
    cudaGetSymbolAddress((void**)&ah,  g_ah);
    cudaGetSymbolAddress((void**)&atb, g_atb);
    cudaGetSymbolAddress((void**)&h2b, g_h2b);
    cudaGetSymbolAddress((void**)&swb, g_swb);
    cudaGetSymbolAddress((void**)&kb,  g_kb);
    cudaGetSymbolAddress((void**)&vb,  g_vb);
    cudaGetSymbolAddress((void**)&bqkv, g_bqkv);
    cudaGetSymbolAddress((void**)&bo_,  g_bo);
    cudaGetSymbolAddress((void**)&b1_,  g_b1);
    cudaGetSymbolAddress((void**)&b2_,  g_b2);

    cudaFuncSetAttribute(gemm_mma, cudaFuncAttributeMaxDynamicSharedMemorySize, GEMM_SMEM);
    cudaFuncSetAttribute(attn_tc,  cudaFuncAttributeMaxDynamicSharedMemorySize, ATT_SMEM);

    // 0) all weight prep in one launch
    prep_all<<<PREP_GRID, 256>>>(Wq, Wk, Wv, Wo, W1, W2, bqkv, bo_, b1_, b2_);

    // 1) ah = split(rmsnorm(x, g1))
    rmsnorm_split<<<NT, 256>>>(x, g1, ah);

    // 2) qkv = ah @ [Wq|Wk|Wv]
    gemm_mma<<<dim3(QKVN / 128, NT / 128), 256, GEMM_SMEM>>>(
        ah, bqkv, nullptr, nullptr, qkv, NT, QKVN, DD);

    // 3) split K/V into per-head hi/lo layouts
    split_kv<<<dim3(TT / 64, BH), 256>>>(qkv, kb, vb);

    // 4) tensor-core attention -> atb (split)
    attn_tc<<<dim3(TT / 128, BH), 256, ATT_SMEM>>>(qkv, kb, vb, atb);

    // 5) x1 = x + atb @ Wo + bo   (<- ncu sample target)
    gemm_mma<<<dim3(DD / 128, NT / 128), 256, GEMM_SMEM>>>(
        atb, bo_, bo, x, x1, NT, DD, DD);

    // 6) h2b = split(rmsnorm(x1, g2))
    rmsnorm_split<<<NT, 256>>>(x1, g2, h2b);

    // 7) u = h2b @ W1 + b1
    gemm_mma<<<dim3(FF / 128, NT / 128), 256, GEMM_SMEM>>>(
        h2b, b1_, b1, nullptr, u, NT, FF, DD);

    // 8) swb = split(swiglu(u))
    swiglu_split<<<(NT * HALF + 255) / 256, 256>>>(u, swb);

    // 9) out = x1 + swb @ W2 + b2
    gemm_mma<<<dim3(DD / 128, NT / 128), 256, GEMM_SMEM>>>(
        swb, b2_, b2, x1, out, NT, DD, HALF);
}